// round 11
// baseline (speedup 1.0000x reference)
#include <cuda_runtime.h>

#define N_NODES 100000
#define E_EDGES 1600000
#define DIMS    3
#define C_CH    32
#define ROW_IN  67   // DIM + F
#define ROW_OUT 35   // DIM + C
#define NB_SCAN 98   // ceil(N/1024)
#define N_GROUPS (N_NODES / 32)           // 3125
#define PAY_CAP (E_EDGES + 8 * N_NODES)   // interleave padding headroom
#define T_TILE  8                          // j-depth per smem tile

typedef unsigned long long u64;

// ---- scratch (static device globals; no allocation) ----
// g_deg is zero at module load and re-zeroed by k_main each run.
__device__ int    g_deg[N_NODES];
__device__ int    g_start[N_NODES];    // interleaved slot: groupBase + laneRank
__device__ int    g_cursor[N_NODES];   // advances by 32 per scattered edge
__device__ int    g_perm[N_NODES];     // nodes sorted by degree within 1024-windows
__device__ int    g_gbase[N_GROUPS];   // payload base per 32-node group
__device__ int    g_gdmax[N_GROUPS];   // max degree per group (uniform loop bound)
__device__ int    g_alloc;
__device__ float4 g_ch[N_NODES];        // {x, y, z, hsum}
__device__ float4 g_payload[PAY_CAP];   // group edge j of rank r at base + j*32 + r

__device__ __forceinline__ float ex2_approx(float x) {
    float r;
    asm("ex2.approx.f32 %0, %1;" : "=f"(r) : "f"(x));
    return r;
}
__device__ __forceinline__ float tanh_approx(float x) {
    float r;
    asm("tanh.approx.f32 %0, %1;" : "=f"(r) : "f"(x));
    return r;
}
__device__ __forceinline__ u64 pack2(float lo, float hi) {
    u64 r; asm("mov.b64 %0, {%1, %2};" : "=l"(r) : "f"(lo), "f"(hi)); return r;
}
__device__ __forceinline__ void unpack2(u64 v, float& lo, float& hi) {
    asm("mov.b64 {%0, %1}, %2;" : "=f"(lo), "=f"(hi) : "l"(v));
}
__device__ __forceinline__ u64 fma2(u64 a, u64 b, u64 c) {
    u64 d; asm("fma.rn.f32x2 %0, %1, %2, %3;" : "=l"(d) : "l"(a), "l"(b), "l"(c)); return d;
}
__device__ __forceinline__ u64 mul2(u64 a, u64 b) {
    u64 d; asm("mul.rn.f32x2 %0, %1, %2;" : "=l"(d) : "l"(a), "l"(b)); return d;
}

// K1: warp per node: hsum, coords->out, packed {coords,hsum}.
// First E threads ALSO histogram one edge each (g_deg arrives zeroed).
__global__ void k_init(const float* __restrict__ feat,
                       const int2*  __restrict__ ei,
                       float*       __restrict__ out) {
    int gtid = blockIdx.x * blockDim.x + threadIdx.x;
    if (gtid == 0) g_alloc = 0;
    if (gtid < E_EDGES) atomicAdd(&g_deg[ei[gtid].x], 1);

    int node = gtid >> 5;
    int lane = gtid & 31;
    if (node >= N_NODES) return;
    const float* row = feat + (size_t)node * ROW_IN;
    float s = row[DIMS + lane] + row[DIMS + 32 + lane];
    #pragma unroll
    for (int o = 16; o > 0; o >>= 1) s += __shfl_xor_sync(0xffffffffu, s, o);
    if (lane == 0) g_ch[node] = make_float4(row[0], row[1], row[2], s);
    if (lane < DIMS) out[(size_t)node * ROW_OUT + lane] = row[lane];
}

// K2: local counting sort of each 1024-node window by clamped degree, then
// per-32-node group: reserve 32*dmax interleaved slots (one atomicAdd),
// record {base, dmax}, and ZERO the padding slots so k_main can run every
// lane to dmax with no bounds checks (zero payload contributes exactly 0).
__global__ void k_alloc() {
    __shared__ int bcur[64];
    __shared__ int sperm[1024];
    int i = blockIdx.x * 1024 + threadIdx.x;
    int lane = threadIdx.x & 31;
    bool valid = i < N_NODES;
    int validCount = N_NODES - blockIdx.x * 1024;
    if (validCount > 1024) validCount = 1024;

    if (threadIdx.x < 64) bcur[threadIdx.x] = 0;
    __syncthreads();

    int d = valid ? g_deg[i] : 0;
    int dc = d < 63 ? d : 63;
    if (valid) atomicAdd(&bcur[dc], 1);
    __syncthreads();
    if (threadIdx.x == 0) {
        int run = 0;
        #pragma unroll
        for (int k = 0; k < 64; k++) { int c = bcur[k]; bcur[k] = run; run += c; }
    }
    __syncthreads();
    if (valid) {
        int pos = atomicAdd(&bcur[dc], 1);
        sperm[pos] = i;                         // dense ranks 0..validCount-1
    }
    __syncthreads();

    int rank = threadIdx.x;
    bool rvalid = rank < validCount;            // whole warps (N % 32 == 0)
    int nd = rvalid ? sperm[rank] : 0;
    int dd = rvalid ? g_deg[nd] : 0;
    int dmax = dd;
    #pragma unroll
    for (int o = 16; o > 0; o >>= 1) {
        int v = __shfl_xor_sync(0xffffffffu, dmax, o);
        dmax = v > dmax ? v : dmax;
    }
    int base = 0;
    if (lane == 0 && dmax > 0) base = atomicAdd(&g_alloc, 32 * dmax);
    base = __shfl_sync(0xffffffffu, base, 0);
    if (rvalid) {
        int group = blockIdx.x * 32 + (rank >> 5);
        g_perm[blockIdx.x * 1024 + rank] = nd;
        if (lane == 0) { g_gbase[group] = base; g_gdmax[group] = dmax; }
        int st = base + lane;
        g_start[nd]  = st;
        g_cursor[nd] = st;
        // zero padding slots [dd, dmax)
        for (int j = dd; j < dmax; j++)
            g_payload[base + j * 32 + lane] = make_float4(0.f, 0.f, 0.f, 0.f);
    }
}

// K3: per-edge (4 edges/thread): u = tanh((c_dst-c_src)@W + b);
// scatter into the interleaved slot (cursor steps by 32).
__global__ void k_scatter(const int2*  __restrict__ ei,
                          const float* __restrict__ w,
                          const float* __restrict__ b) {
    int t = blockIdx.x * blockDim.x + threadIdx.x;
    if (t >= E_EDGES / 4) return;
    #pragma unroll
    for (int k = 0; k < 4; k++) {
        int e = t + k * (E_EDGES / 4);
        int2 sd = ei[e];
        float4 cs = __ldg(&g_ch[sd.x]);
        float4 cd = __ldg(&g_ch[sd.y]);
        float dx = cd.x - cs.x;
        float dy = cd.y - cs.y;
        float dz = cd.z - cs.z;
        float u0 = tanh_approx(fmaf(dz, w[6], fmaf(dy, w[3], fmaf(dx, w[0], b[0]))));
        float u1 = tanh_approx(fmaf(dz, w[7], fmaf(dy, w[4], fmaf(dx, w[1], b[1]))));
        float u2 = tanh_approx(fmaf(dz, w[8], fmaf(dy, w[5], fmaf(dx, w[2], b[2]))));
        int pos = atomicAdd(&g_cursor[sd.x], 32);
        g_payload[pos] = make_float4(u0, u1, u2, cd.w);
    }
}

// K4: block = one 32-node group x 8 chunk-warps of 4 channels.
// Payload staged through smem tiles: one coalesced float4 per thread per
// tile (full MLP, bulk-sync), then 8 warps read via conflict-free LDS.128.
// Uniform loop to dmax: no divergence, no bounds checks (padding is zeroed).
__global__ void __launch_bounds__(256) k_main(const float* __restrict__ mu,
                                              const float* __restrict__ sig,
                                              float*       __restrict__ out) {
    __shared__ float4 tile[T_TILE * 32];          // 4KB
    int lane  = threadIdx.x & 31;
    int chunk = threadIdx.x >> 5;                 // 0..7, 4 channels each
    int group = blockIdx.x;
    int node  = g_perm[group * 32 + lane];

    int base = g_gbase[group];
    int dmax = g_gdmax[group];
    if (chunk == 0) g_deg[node] = 0;              // reset for next replay

    const float NHL2E = -0.7213475204444817f;     // -0.5 * log2(e)

    u64 a0p[2], a1p[2], a2p[2], b0p[2], b1p[2], b2p[2], ccp[2], accp[2];
    #pragma unroll
    for (int c = 0; c < 2; c++) {
        float a0[2], a1[2], a2[2], bb0[2], bb1[2], bb2[2], cc[2];
        #pragma unroll
        for (int h = 0; h < 2; h++) {
            int ch = chunk * 4 + c * 2 + h;
            size_t bi = (size_t)ch * (size_t)N_NODES * 3 + (size_t)node * 3;
            float m0 = __ldg(&mu[bi + 0]);
            float m1 = __ldg(&mu[bi + 1]);
            float m2 = __ldg(&mu[bi + 2]);
            a0[h] = __fdividef(NHL2E, __ldg(&sig[bi + 0]));
            a1[h] = __fdividef(NHL2E, __ldg(&sig[bi + 1]));
            a2[h] = __fdividef(NHL2E, __ldg(&sig[bi + 2]));
            bb0[h] = -2.0f * a0[h] * m0;
            bb1[h] = -2.0f * a1[h] * m1;
            bb2[h] = -2.0f * a2[h] * m2;
            cc[h]  = fmaf(a2[h], m2 * m2, fmaf(a1[h], m1 * m1, a0[h] * m0 * m0));
        }
        a0p[c] = pack2(a0[0], a0[1]);
        a1p[c] = pack2(a1[0], a1[1]);
        a2p[c] = pack2(a2[0], a2[1]);
        b0p[c] = pack2(bb0[0], bb0[1]);
        b1p[c] = pack2(bb1[0], bb1[1]);
        b2p[c] = pack2(bb2[0], bb2[1]);
        ccp[c] = pack2(cc[0], cc[1]);
        accp[c] = 0ull;
    }

    for (int t0 = 0; t0 < dmax; t0 += T_TILE) {
        int cnt = dmax - t0;
        if (cnt > T_TILE) cnt = T_TILE;
        __syncthreads();                          // previous tile fully consumed
        if (threadIdx.x < cnt * 32)
            tile[threadIdx.x] = __ldg(&g_payload[base + t0 * 32 + threadIdx.x]);
        __syncthreads();
        for (int j = 0; j < cnt; j++) {
            float4 p = tile[j * 32 + lane];
            u64 px = pack2(p.x, p.x);
            u64 py = pack2(p.y, p.y);
            u64 pz = pack2(p.z, p.z);
            u64 pw = pack2(p.w, p.w);
            u64 q0 = mul2(px, px);
            u64 q1 = mul2(py, py);
            u64 q2 = mul2(pz, pz);
            #pragma unroll
            for (int c = 0; c < 2; c++) {
                u64 s = fma2(a0p[c], q0, ccp[c]);
                s = fma2(b0p[c], px, s);
                s = fma2(a1p[c], q1, s);
                s = fma2(b1p[c], py, s);
                s = fma2(a2p[c], q2, s);
                s = fma2(b2p[c], pz, s);
                float slo, shi;
                unpack2(s, slo, shi);
                u64 e = pack2(ex2_approx(slo), ex2_approx(shi));
                accp[c] = fma2(e, pw, accp[c]);
            }
        }
    }

    float* o = out + (size_t)node * ROW_OUT + DIMS + chunk * 4;
    #pragma unroll
    for (int c = 0; c < 2; c++) {
        float lo, hi;
        unpack2(accp[c], lo, hi);
        o[c * 2 + 0] = lo;
        o[c * 2 + 1] = hi;
    }
}

extern "C" void kernel_launch(void* const* d_in, const int* in_sizes, int n_in,
                              void* d_out, int out_size) {
    const float* feat = (const float*)d_in[0];
    const int*   ei   = (const int*)d_in[1];
    const float* w    = (const float*)d_in[2];
    const float* b    = (const float*)d_in[3];
    const float* mu   = (const float*)d_in[4];
    const float* sig  = (const float*)d_in[5];
    float* out = (float*)d_out;

    int blkNodeWarps = (N_NODES * 32 + 255) / 256;   // 12500
    int blkScatter   = (E_EDGES / 4 + 255) / 256;    // 1563

    k_init<<<blkNodeWarps, 256>>>(feat, (const int2*)ei, out);
    k_alloc<<<NB_SCAN, 1024>>>();
    k_scatter<<<blkScatter, 256>>>((const int2*)ei, w, b);
    k_main<<<N_GROUPS, 256>>>(mu, sig, out);
}

// round 12
// speedup vs baseline: 1.0381x; 1.0381x over previous
#include <cuda_runtime.h>

#define N_NODES 100000
#define E_EDGES 1600000
#define DIMS    3
#define C_CH    32
#define ROW_IN  67   // DIM + F
#define ROW_OUT 35   // DIM + C
#define NB_SCAN 98   // ceil(N/1024)
#define N_GROUPS (N_NODES / 32)           // 3125
#define PAY_CAP (E_EDGES + 8 * N_NODES)   // interleave padding headroom
#define T_TILE  8                          // j-depth per smem tile (256 float4)

typedef unsigned long long u64;

// ---- scratch (static device globals; no allocation) ----
// g_deg is zero at module load and re-zeroed by k_main each run.
__device__ int    g_deg[N_NODES];
__device__ int    g_start[N_NODES];    // interleaved slot: groupBase + laneRank
__device__ int    g_cursor[N_NODES];   // advances by 32 per scattered edge
__device__ int    g_perm[N_NODES];     // nodes sorted by degree within 1024-windows
__device__ int    g_gbase[N_GROUPS];   // payload base per 32-node group
__device__ int    g_gdmax[N_GROUPS];   // max degree per group (uniform loop bound)
__device__ int    g_alloc;
__device__ float4 g_ch[N_NODES];        // {x, y, z, hsum}
__device__ float4 g_payload[PAY_CAP];   // group edge j of rank r at base + j*32 + r

__device__ __forceinline__ float ex2_approx(float x) {
    float r;
    asm("ex2.approx.f32 %0, %1;" : "=f"(r) : "f"(x));
    return r;
}
__device__ __forceinline__ float tanh_approx(float x) {
    float r;
    asm("tanh.approx.f32 %0, %1;" : "=f"(r) : "f"(x));
    return r;
}
__device__ __forceinline__ u64 pack2(float lo, float hi) {
    u64 r; asm("mov.b64 %0, {%1, %2};" : "=l"(r) : "f"(lo), "f"(hi)); return r;
}
__device__ __forceinline__ void unpack2(u64 v, float& lo, float& hi) {
    asm("mov.b64 {%0, %1}, %2;" : "=f"(lo), "=f"(hi) : "l"(v));
}
__device__ __forceinline__ u64 fma2(u64 a, u64 b, u64 c) {
    u64 d; asm("fma.rn.f32x2 %0, %1, %2, %3;" : "=l"(d) : "l"(a), "l"(b), "l"(c)); return d;
}
__device__ __forceinline__ u64 mul2(u64 a, u64 b) {
    u64 d; asm("mul.rn.f32x2 %0, %1, %2;" : "=l"(d) : "l"(a), "l"(b)); return d;
}

// K1: warp per node: hsum, coords->out, packed {coords,hsum}.
// First E threads ALSO histogram one edge each (g_deg arrives zeroed).
__global__ void k_init(const float* __restrict__ feat,
                       const int2*  __restrict__ ei,
                       float*       __restrict__ out) {
    int gtid = blockIdx.x * blockDim.x + threadIdx.x;
    if (gtid == 0) g_alloc = 0;
    if (gtid < E_EDGES) atomicAdd(&g_deg[ei[gtid].x], 1);

    int node = gtid >> 5;
    int lane = gtid & 31;
    if (node >= N_NODES) return;
    const float* row = feat + (size_t)node * ROW_IN;
    float s = row[DIMS + lane] + row[DIMS + 32 + lane];
    #pragma unroll
    for (int o = 16; o > 0; o >>= 1) s += __shfl_xor_sync(0xffffffffu, s, o);
    if (lane == 0) g_ch[node] = make_float4(row[0], row[1], row[2], s);
    if (lane < DIMS) out[(size_t)node * ROW_OUT + lane] = row[lane];
}

// K2: local counting sort of each 1024-node window by clamped degree, then
// per-32-node group: reserve 32*dmax interleaved slots (one atomicAdd),
// record {base, dmax}, zero padding slots [deg, dmax).
__global__ void k_alloc() {
    __shared__ int bcur[64];
    __shared__ int sperm[1024];
    int i = blockIdx.x * 1024 + threadIdx.x;
    int lane = threadIdx.x & 31;
    bool valid = i < N_NODES;
    int validCount = N_NODES - blockIdx.x * 1024;
    if (validCount > 1024) validCount = 1024;

    if (threadIdx.x < 64) bcur[threadIdx.x] = 0;
    __syncthreads();

    int d = valid ? g_deg[i] : 0;
    int dc = d < 63 ? d : 63;
    if (valid) atomicAdd(&bcur[dc], 1);
    __syncthreads();
    if (threadIdx.x == 0) {
        int run = 0;
        #pragma unroll
        for (int k = 0; k < 64; k++) { int c = bcur[k]; bcur[k] = run; run += c; }
    }
    __syncthreads();
    if (valid) {
        int pos = atomicAdd(&bcur[dc], 1);
        sperm[pos] = i;                         // dense ranks 0..validCount-1
    }
    __syncthreads();

    int rank = threadIdx.x;
    bool rvalid = rank < validCount;            // whole warps (N % 32 == 0)
    int nd = rvalid ? sperm[rank] : 0;
    int dd = rvalid ? g_deg[nd] : 0;
    int dmax = dd;
    #pragma unroll
    for (int o = 16; o > 0; o >>= 1) {
        int v = __shfl_xor_sync(0xffffffffu, dmax, o);
        dmax = v > dmax ? v : dmax;
    }
    int base = 0;
    if (lane == 0 && dmax > 0) base = atomicAdd(&g_alloc, 32 * dmax);
    base = __shfl_sync(0xffffffffu, base, 0);
    if (rvalid) {
        int group = blockIdx.x * 32 + (rank >> 5);
        g_perm[blockIdx.x * 1024 + rank] = nd;
        if (lane == 0) { g_gbase[group] = base; g_gdmax[group] = dmax; }
        int st = base + lane;
        g_start[nd]  = st;
        g_cursor[nd] = st;
        for (int j = dd; j < dmax; j++)
            g_payload[base + j * 32 + lane] = make_float4(0.f, 0.f, 0.f, 0.f);
    }
}

// K3: per-edge (4 edges/thread): u = tanh((c_dst-c_src)@W + b);
// scatter into the interleaved slot (cursor steps by 32).
__global__ void k_scatter(const int2*  __restrict__ ei,
                          const float* __restrict__ w,
                          const float* __restrict__ b) {
    int t = blockIdx.x * blockDim.x + threadIdx.x;
    if (t >= E_EDGES / 4) return;
    #pragma unroll
    for (int k = 0; k < 4; k++) {
        int e = t + k * (E_EDGES / 4);
        int2 sd = ei[e];
        float4 cs = __ldg(&g_ch[sd.x]);
        float4 cd = __ldg(&g_ch[sd.y]);
        float dx = cd.x - cs.x;
        float dy = cd.y - cs.y;
        float dz = cd.z - cs.z;
        float u0 = tanh_approx(fmaf(dz, w[6], fmaf(dy, w[3], fmaf(dx, w[0], b[0]))));
        float u1 = tanh_approx(fmaf(dz, w[7], fmaf(dy, w[4], fmaf(dx, w[1], b[1]))));
        float u2 = tanh_approx(fmaf(dz, w[8], fmaf(dy, w[5], fmaf(dx, w[2], b[2]))));
        int pos = atomicAdd(&g_cursor[sd.x], 32);
        g_payload[pos] = make_float4(u0, u1, u2, cd.w);
    }
}

// K4: block = one 32-node group x 8 chunk-warps of 4 channels.
// Double-buffered smem pipeline: STS tile t -> one sync -> issue LDG for
// tile t+1 (hidden behind compute) -> compute tile t. One barrier per tile.
// Loads are unguarded fixed-shape (reads past dmax stay in g_payload headroom
// and are never consumed; compute bounded by cnt).
__global__ void __launch_bounds__(256) k_main(const float* __restrict__ mu,
                                              const float* __restrict__ sig,
                                              float*       __restrict__ out) {
    __shared__ float4 buf[2][T_TILE * 32];        // 2 x 4KB
    int lane  = threadIdx.x & 31;
    int chunk = threadIdx.x >> 5;                 // 0..7, 4 channels each
    int group = blockIdx.x;
    int node  = g_perm[group * 32 + lane];

    int base = g_gbase[group];
    int dmax = g_gdmax[group];
    if (chunk == 0) g_deg[node] = 0;              // reset for next replay

    const float NHL2E = -0.7213475204444817f;     // -0.5 * log2(e)

    // first tile load issued BEFORE the coefficient prologue: LDG latency
    // overlaps the 12 scattered mu/sig gathers + MUFU divides below.
    float4 v = __ldg(&g_payload[base + threadIdx.x]);

    u64 a0p[2], a1p[2], a2p[2], b0p[2], b1p[2], b2p[2], ccp[2], accp[2];
    #pragma unroll
    for (int c = 0; c < 2; c++) {
        float a0[2], a1[2], a2[2], bb0[2], bb1[2], bb2[2], cc[2];
        #pragma unroll
        for (int h = 0; h < 2; h++) {
            int ch = chunk * 4 + c * 2 + h;
            size_t bi = (size_t)ch * (size_t)N_NODES * 3 + (size_t)node * 3;
            float m0 = __ldg(&mu[bi + 0]);
            float m1 = __ldg(&mu[bi + 1]);
            float m2 = __ldg(&mu[bi + 2]);
            a0[h] = __fdividef(NHL2E, __ldg(&sig[bi + 0]));
            a1[h] = __fdividef(NHL2E, __ldg(&sig[bi + 1]));
            a2[h] = __fdividef(NHL2E, __ldg(&sig[bi + 2]));
            bb0[h] = -2.0f * a0[h] * m0;
            bb1[h] = -2.0f * a1[h] * m1;
            bb2[h] = -2.0f * a2[h] * m2;
            cc[h]  = fmaf(a2[h], m2 * m2, fmaf(a1[h], m1 * m1, a0[h] * m0 * m0));
        }
        a0p[c] = pack2(a0[0], a0[1]);
        a1p[c] = pack2(a1[0], a1[1]);
        a2p[c] = pack2(a2[0], a2[1]);
        b0p[c] = pack2(bb0[0], bb0[1]);
        b1p[c] = pack2(bb1[0], bb1[1]);
        b2p[c] = pack2(bb2[0], bb2[1]);
        ccp[c] = pack2(cc[0], cc[1]);
        accp[c] = 0ull;
    }

    int ntiles = (dmax + T_TILE - 1) / T_TILE;
    for (int t = 0; t < ntiles; t++) {
        buf[t & 1][threadIdx.x] = v;
        __syncthreads();                          // tile t visible; buf[(t+1)&1] free
        if (t + 1 < ntiles)
            v = __ldg(&g_payload[base + (t + 1) * (T_TILE * 32) + threadIdx.x]);
        int cnt = dmax - t * T_TILE;
        if (cnt > T_TILE) cnt = T_TILE;
        for (int j = 0; j < cnt; j++) {
            float4 p = buf[t & 1][j * 32 + lane];
            u64 px = pack2(p.x, p.x);
            u64 py = pack2(p.y, p.y);
            u64 pz = pack2(p.z, p.z);
            u64 pw = pack2(p.w, p.w);
            u64 q0 = mul2(px, px);
            u64 q1 = mul2(py, py);
            u64 q2 = mul2(pz, pz);
            #pragma unroll
            for (int c = 0; c < 2; c++) {
                u64 s = fma2(a0p[c], q0, ccp[c]);
                s = fma2(b0p[c], px, s);
                s = fma2(a1p[c], q1, s);
                s = fma2(b1p[c], py, s);
                s = fma2(a2p[c], q2, s);
                s = fma2(b2p[c], pz, s);
                float slo, shi;
                unpack2(s, slo, shi);
                u64 e = pack2(ex2_approx(slo), ex2_approx(shi));
                accp[c] = fma2(e, pw, accp[c]);
            }
        }
    }

    float* o = out + (size_t)node * ROW_OUT + DIMS + chunk * 4;
    #pragma unroll
    for (int c = 0; c < 2; c++) {
        float lo, hi;
        unpack2(accp[c], lo, hi);
        o[c * 2 + 0] = lo;
        o[c * 2 + 1] = hi;
    }
}

extern "C" void kernel_launch(void* const* d_in, const int* in_sizes, int n_in,
                              void* d_out, int out_size) {
    const float* feat = (const float*)d_in[0];
    const int*   ei   = (const int*)d_in[1];
    const float* w    = (const float*)d_in[2];
    const float* b    = (const float*)d_in[3];
    const float* mu   = (const float*)d_in[4];
    const float* sig  = (const float*)d_in[5];
    float* out = (float*)d_out;

    int blkNodeWarps = (N_NODES * 32 + 255) / 256;   // 12500
    int blkScatter   = (E_EDGES / 4 + 255) / 256;    // 1563

    k_init<<<blkNodeWarps, 256>>>(feat, (const int2*)ei, out);
    k_alloc<<<NB_SCAN, 1024>>>();
    k_scatter<<<blkScatter, 256>>>((const int2*)ei, w, b);
    k_main<<<N_GROUPS, 256>>>(mu, sig, out);
}